// round 1
// baseline (speedup 1.0000x reference)
#include <cuda_runtime.h>
#include <cstdint>

// Problem constants
#define BDIM 1024
#define LDIM 2
#define DDIM 1024
#define FDIM 32768
#define KENC (LDIM * DDIM)          // 2048
#define NSPLIT 8
#define KSPLIT (FDIM / NSPLIT)      // 4096

// Scratch (device globals: allocation-guard safe)
__device__ float g_f[(size_t)BDIM * FDIM];                 // 128 MB encoder output
__device__ float g_partial[(size_t)NSPLIT * BDIM * KENC];  // 64 MB split-K partials

// ---------------------------------------------------------------------------
// helpers
// ---------------------------------------------------------------------------
__device__ __forceinline__ uint32_t f2tf(float x) {
    uint32_t r;
    asm volatile("cvt.rna.tf32.f32 %0, %1;" : "=r"(r) : "f"(x));
    return r;
}

__device__ __forceinline__ void cp16(uint32_t dst, const void* src) {
    asm volatile("cp.async.cg.shared.global [%0], [%1], 16;" :: "r"(dst), "l"(src));
}

__device__ __forceinline__ void mma_tf32(float c[4],
                                         const uint32_t a[4],
                                         const uint32_t b[2]) {
    asm volatile(
        "mma.sync.aligned.m16n8k8.row.col.f32.tf32.tf32.f32 "
        "{%0,%1,%2,%3}, {%4,%5,%6,%7}, {%8,%9}, {%0,%1,%2,%3};"
        : "+f"(c[0]), "+f"(c[1]), "+f"(c[2]), "+f"(c[3])
        : "r"(a[0]), "r"(a[1]), "r"(a[2]), "r"(a[3]),
          "r"(b[0]), "r"(b[1]));
}

// ---------------------------------------------------------------------------
// GEMM core: C[128,128] tile = A[128,K] * B[K,128]  (A row-major, B row-major)
// BK = 16, double-buffered cp.async. 256 threads = 8 warps (2m x 4n).
// ---------------------------------------------------------------------------
template <bool BIAS, bool RELU>
__device__ __forceinline__ void gemm_core(
    const float* __restrict__ A, int lda,
    const float* __restrict__ B, int ldb,
    float* __restrict__ C, int ldc,
    int kTiles, const float* __restrict__ bias)
{
    __shared__ float As[2][128][20];   // [m][k], pad 20 -> conflict-free frags
    __shared__ float Bs[2][16][136];   // [k][n], pad 136 -> conflict-free frags

    const int tid  = threadIdx.x;
    const int lane = tid & 31;
    const int warp = tid >> 5;
    const int wm = (warp & 1) << 6;    // 0 / 64
    const int wn = (warp >> 1) << 5;   // 0 / 32 / 64 / 96
    const int ty = lane >> 2;          // 0..7
    const int tc = lane & 3;           // 0..3

    float acc[4][4][4];
#pragma unroll
    for (int mt = 0; mt < 4; mt++)
#pragma unroll
        for (int nt = 0; nt < 4; nt++)
#pragma unroll
            for (int i = 0; i < 4; i++) acc[mt][nt][i] = 0.f;

    const uint32_t aBase = (uint32_t)__cvta_generic_to_shared(&As[0][0][0]);
    const uint32_t bBase = (uint32_t)__cvta_generic_to_shared(&Bs[0][0][0]);

    // A chunks: 128 rows * 4 chunks(16B) = 512 ; B chunks: 16 rows * 32 = 512
    const int acr0 = tid >> 2,  acc0 = tid & 3;       // chunk tid
    const int acr1 = (tid + 256) >> 2, acc1 = (tid + 256) & 3;
    const int bcr0 = tid >> 5,  bcc0 = tid & 31;
    const int bcr1 = (tid + 256) >> 5, bcc1 = (tid + 256) & 31;

#define LOAD_TILE(buf, kt)                                                         \
    do {                                                                           \
        cp16(aBase + (((buf)*128 + acr0) * 20 + acc0 * 4) * 4,                     \
             A + (size_t)acr0 * lda + (size_t)(kt) * 16 + acc0 * 4);               \
        cp16(aBase + (((buf)*128 + acr1) * 20 + acc1 * 4) * 4,                     \
             A + (size_t)acr1 * lda + (size_t)(kt) * 16 + acc1 * 4);               \
        cp16(bBase + (((buf)*16 + bcr0) * 136 + bcc0 * 4) * 4,                     \
             B + (size_t)((kt) * 16 + bcr0) * ldb + bcc0 * 4);                     \
        cp16(bBase + (((buf)*16 + bcr1) * 136 + bcc1 * 4) * 4,                     \
             B + (size_t)((kt) * 16 + bcr1) * ldb + bcc1 * 4);                     \
        asm volatile("cp.async.commit_group;");                                    \
    } while (0)

    LOAD_TILE(0, 0);

    int buf = 0;
    for (int kt = 0; kt < kTiles; kt++) {
        if (kt + 1 < kTiles) {
            LOAD_TILE(buf ^ 1, kt + 1);
            asm volatile("cp.async.wait_group 1;");
        } else {
            asm volatile("cp.async.wait_group 0;");
        }
        __syncthreads();

#pragma unroll
        for (int ks = 0; ks < 2; ks++) {
            uint32_t af[4][4];
            uint32_t bf[4][2];
#pragma unroll
            for (int mt = 0; mt < 4; mt++) {
                const int r = wm + mt * 16 + ty;
                const int c = ks * 8 + tc;
                af[mt][0] = f2tf(As[buf][r][c]);
                af[mt][1] = f2tf(As[buf][r + 8][c]);
                af[mt][2] = f2tf(As[buf][r][c + 4]);
                af[mt][3] = f2tf(As[buf][r + 8][c + 4]);
            }
#pragma unroll
            for (int nt = 0; nt < 4; nt++) {
                const int rk = ks * 8 + tc;
                const int cn = wn + nt * 8 + ty;
                bf[nt][0] = f2tf(Bs[buf][rk][cn]);
                bf[nt][1] = f2tf(Bs[buf][rk + 4][cn]);
            }
#pragma unroll
            for (int mt = 0; mt < 4; mt++)
#pragma unroll
                for (int nt = 0; nt < 4; nt++)
                    mma_tf32(acc[mt][nt], af[mt], bf[nt]);
        }
        __syncthreads();
        buf ^= 1;
    }
#undef LOAD_TILE

    // epilogue
#pragma unroll
    for (int mt = 0; mt < 4; mt++) {
#pragma unroll
        for (int nt = 0; nt < 4; nt++) {
            const int r = wm + mt * 16 + ty;
            const int cidx = wn + nt * 8 + tc * 2;
            float2 v0 = make_float2(acc[mt][nt][0], acc[mt][nt][1]);
            float2 v1 = make_float2(acc[mt][nt][2], acc[mt][nt][3]);
            if (BIAS) {
                const float b0 = bias[cidx], b1 = bias[cidx + 1];
                v0.x += b0; v0.y += b1; v1.x += b0; v1.y += b1;
            }
            if (RELU) {
                v0.x = fmaxf(v0.x, 0.f); v0.y = fmaxf(v0.y, 0.f);
                v1.x = fmaxf(v1.x, 0.f); v1.y = fmaxf(v1.y, 0.f);
            }
            *(float2*)(C + (size_t)r * ldc + cidx)       = v0;
            *(float2*)(C + (size_t)(r + 8) * ldc + cidx) = v1;
        }
    }
}

// ---------------------------------------------------------------------------
// Encoder: f[1024, 32768] = relu(x[1024,2048] @ W_enc[2048,32768] + b_enc)
// grid (256 n, 8 m)
// ---------------------------------------------------------------------------
__global__ void __launch_bounds__(256, 2) enc_kernel(
    const float* __restrict__ x,
    const float* __restrict__ Wenc,
    const float* __restrict__ benc)
{
    const float* A = x + (size_t)blockIdx.y * 128 * KENC;
    const float* B = Wenc + (size_t)blockIdx.x * 128;
    float* C = g_f + (size_t)blockIdx.y * 128 * FDIM + (size_t)blockIdx.x * 128;
    gemm_core<true, true>(A, KENC, B, FDIM, C, FDIM, KENC / 16,
                          benc + blockIdx.x * 128);
}

// ---------------------------------------------------------------------------
// Decoder split-K: partial[s][1024][2048] = f[:, s*4096:(s+1)*4096] @ W_dec[l]
// grid (8 n-per-l, 8 m, 16 = split*2 + l)
// ---------------------------------------------------------------------------
__global__ void __launch_bounds__(256, 2) dec_kernel(const float* __restrict__ Wdec)
{
    const int split = blockIdx.z >> 1;
    const int l     = blockIdx.z & 1;
    const float* A = g_f + (size_t)blockIdx.y * 128 * FDIM + (size_t)split * KSPLIT;
    const float* B = Wdec + (size_t)l * FDIM * DDIM
                          + (size_t)split * KSPLIT * DDIM
                          + (size_t)blockIdx.x * 128;
    float* C = g_partial + (size_t)split * BDIM * KENC
                         + (size_t)blockIdx.y * 128 * KENC
                         + (size_t)l * DDIM + (size_t)blockIdx.x * 128;
    gemm_core<false, false>(A, FDIM, B, DDIM, C, KENC, KSPLIT / 16, nullptr);
}

// ---------------------------------------------------------------------------
// Reduce: out[b, l*D+d] = b_dec[l*D+d] + sum_s partial[s][b][l*D+d]
// 2M floats = 524288 float4 ; grid 2048 x 256
// ---------------------------------------------------------------------------
__global__ void __launch_bounds__(256) reduce_kernel(
    const float* __restrict__ bdec, float* __restrict__ out)
{
    const int i = blockIdx.x * blockDim.x + threadIdx.x;  // float4 index
    float4 s = reinterpret_cast<const float4*>(bdec)[i & 511];
#pragma unroll
    for (int p = 0; p < NSPLIT; p++) {
        float4 v = reinterpret_cast<const float4*>(g_partial)[(size_t)p * 524288 + i];
        s.x += v.x; s.y += v.y; s.z += v.z; s.w += v.w;
    }
    reinterpret_cast<float4*>(out)[i] = s;
}

// ---------------------------------------------------------------------------
extern "C" void kernel_launch(void* const* d_in, const int* in_sizes, int n_in,
                              void* d_out, int out_size)
{
    const float* x    = (const float*)d_in[0];   // [1024, 2, 1024]
    const float* Wenc = (const float*)d_in[1];   // [2, 1024, 32768]
    const float* benc = (const float*)d_in[2];   // [32768]
    const float* Wdec = (const float*)d_in[3];   // [2, 32768, 1024]
    const float* bdec = (const float*)d_in[4];   // [2, 1024]
    float* out = (float*)d_out;                  // [1024, 2, 1024]

    enc_kernel<<<dim3(FDIM / 128, BDIM / 128), 256>>>(x, Wenc, benc);
    dec_kernel<<<dim3(DDIM / 128, BDIM / 128, NSPLIT * LDIM), 256>>>(Wdec);
    reduce_kernel<<<(BDIM * KENC / 4) / 256, 256>>>(bdec, out);
}